// round 1
// baseline (speedup 1.0000x reference)
#include <cuda_runtime.h>

#define BM 64
#define BN 64
#define DH 128
#define PSTRIDE 68
#define NTHREADS 256

typedef unsigned long long u64;

// ---- packed fp32x2 helpers (Blackwell dual-fp32 pipe, PTX-only) ----
__device__ __forceinline__ u64 pack2(float x, float y) {
    u64 r; asm("mov.b64 %0, {%1, %2};" : "=l"(r) : "f"(x), "f"(y)); return r;
}
__device__ __forceinline__ float2 unpack2(u64 v) {
    float x, y; asm("mov.b64 {%0, %1}, %2;" : "=f"(x), "=f"(y) : "l"(v));
    return make_float2(x, y);
}
__device__ __forceinline__ u64 fma2(u64 a, u64 b, u64 c) {
    u64 d; asm("fma.rn.f32x2 %0, %1, %2, %3;" : "=l"(d) : "l"(a), "l"(b), "l"(c)); return d;
}
__device__ __forceinline__ u64 mul2(u64 a, u64 b) {
    u64 d; asm("mul.rn.f32x2 %0, %1, %2;" : "=l"(d) : "l"(a), "l"(b)); return d;
}

// XOR swizzle on 16B chunks: chunk c4 of row r stored at c4 ^ ((r>>2)&7).
// Makes both the K-column reads (stride-4 rows across tx) and the V-row reads
// conflict-free without padding.
#define SWC(row, c4) (((c4) ^ (((row) >> 2) & 7)))

__global__ void __launch_bounds__(NTHREADS, 1)
fa_fwd(const float* __restrict__ Q, const float* __restrict__ K,
       const float* __restrict__ V, const int* __restrict__ causal_flag,
       float* __restrict__ O, int S, int H)
{
    extern __shared__ float smem[];
    float* Qs = smem;               // [BM][DH], swizzled 16B chunks
    float* Ks = Qs + BM * DH;       // [BN][DH], swizzled
    float* Vs = Ks + BN * DH;       // [BN][DH], swizzled
    float* Pt = Vs + BN * DH;       // [BN][PSTRIDE]  P^T (kv-row major)

    const int tid = threadIdx.x;
    const int tx  = tid & 15;       // 16 col-groups
    const int ty  = tid >> 4;       // 16 row-groups
    const int qi  = gridDim.x - 1 - blockIdx.x;  // longest CTAs first
    const int h   = blockIdx.y;
    const int b   = blockIdx.z;
    const bool causal = (causal_flag[0] != 0);

    const int q0 = qi * BM;
    const int rowstride = H * DH;
    const float scale = 0.08838834764831845f;   // 1/sqrt(128)

    // ---- load Q tile (coalesced: one warp = one 512B row) ----
    {
        const float* qg = Q + (size_t)(b * S + q0) * rowstride + h * DH;
        for (int idx = tid; idx < BM * 32; idx += NTHREADS) {
            int r = idx >> 5, c4 = idx & 31;
            float4 val = *(const float4*)(qg + r * rowstride + c4 * 4);
            *(float4*)(Qs + r * DH + SWC(r, c4) * 4) = val;
        }
    }

    u64 acc[4][4];                  // 4 rows x 4 col-pairs (8 cols) of O
    float m_i[4], l_i[4];
    #pragma unroll
    for (int i = 0; i < 4; i++) {
        m_i[i] = -1e30f;
        l_i[i] = 0.0f;
        #pragma unroll
        for (int c = 0; c < 4; c++) acc[i][c] = 0ull;
    }

    const int ntiles = causal ? (qi + 1) : (S / BN);

    for (int j = 0; j < ntiles; j++) {
        __syncthreads();   // prior-iter readers of Ks/Vs/Pt done

        // ---- load K,V tiles ----
        {
            const float* kg = K + (size_t)(b * S + j * BN) * rowstride + h * DH;
            const float* vg = V + (size_t)(b * S + j * BN) * rowstride + h * DH;
            for (int idx = tid; idx < BN * 32; idx += NTHREADS) {
                int r = idx >> 5, c4 = idx & 31;
                *(float4*)(Ks + r * DH + SWC(r, c4) * 4) =
                    *(const float4*)(kg + r * rowstride + c4 * 4);
                *(float4*)(Vs + r * DH + SWC(r, c4) * 4) =
                    *(const float4*)(vg + r * rowstride + c4 * 4);
            }
        }
        __syncthreads();

        // ---- S = Q K^T  (f32x2-packed along D) ----
        u64 s2[4][4];
        #pragma unroll
        for (int i = 0; i < 4; i++)
            #pragma unroll
            for (int c = 0; c < 4; c++) s2[i][c] = 0ull;

        #pragma unroll 2
        for (int kk = 0; kk < DH; kk += 4) {
            const int qc = ((kk >> 2) ^ (ty & 7)) * 4;
            const int kc = ((kk >> 2) ^ (tx & 7)) * 4;
            float4 av[4], bv[4];
            #pragma unroll
            for (int i = 0; i < 4; i++)
                av[i] = *(const float4*)(Qs + (ty * 4 + i) * DH + qc);
            #pragma unroll
            for (int jj = 0; jj < 4; jj++)
                bv[jj] = *(const float4*)(Ks + (tx * 4 + jj) * DH + kc);
            u64 alo[4], ahi[4], blo[4], bhi[4];
            #pragma unroll
            for (int i = 0; i < 4; i++) {
                alo[i] = pack2(av[i].x, av[i].y);
                ahi[i] = pack2(av[i].z, av[i].w);
            }
            #pragma unroll
            for (int jj = 0; jj < 4; jj++) {
                blo[jj] = pack2(bv[jj].x, bv[jj].y);
                bhi[jj] = pack2(bv[jj].z, bv[jj].w);
            }
            #pragma unroll
            for (int i = 0; i < 4; i++)
                #pragma unroll
                for (int jj = 0; jj < 4; jj++) {
                    s2[i][jj] = fma2(alo[i], blo[jj], s2[i][jj]);
                    s2[i][jj] = fma2(ahi[i], bhi[jj], s2[i][jj]);
                }
        }

        float sv[4][4];
        #pragma unroll
        for (int i = 0; i < 4; i++)
            #pragma unroll
            for (int jj = 0; jj < 4; jj++) {
                float2 t = unpack2(s2[i][jj]);
                sv[i][jj] = (t.x + t.y) * scale;
            }

        // causal mask only ever needed on the diagonal tile (BM==BN, aligned)
        if (causal && j == qi) {
            #pragma unroll
            for (int i = 0; i < 4; i++) {
                int r = ty * 4 + i;
                #pragma unroll
                for (int jj = 0; jj < 4; jj++) {
                    int c = tx * 4 + jj;
                    if (c > r) sv[i][jj] = -3.0e38f;
                }
            }
        }

        // ---- online softmax (row reduce across the 16 tx lanes) ----
        float p[4][4];
        #pragma unroll
        for (int i = 0; i < 4; i++) {
            float rmax = fmaxf(fmaxf(sv[i][0], sv[i][1]), fmaxf(sv[i][2], sv[i][3]));
            #pragma unroll
            for (int w = 8; w >= 1; w >>= 1)
                rmax = fmaxf(rmax, __shfl_xor_sync(0xffffffffu, rmax, w));
            float mnew  = fmaxf(m_i[i], rmax);
            float alpha = __expf(m_i[i] - mnew);
            m_i[i] = mnew;
            float rsum = 0.0f;
            #pragma unroll
            for (int jj = 0; jj < 4; jj++) {
                p[i][jj] = __expf(sv[i][jj] - mnew);
                rsum += p[i][jj];
            }
            #pragma unroll
            for (int w = 8; w >= 1; w >>= 1)
                rsum += __shfl_xor_sync(0xffffffffu, rsum, w);
            l_i[i] = l_i[i] * alpha + rsum;
            u64 a2 = pack2(alpha, alpha);
            #pragma unroll
            for (int c = 0; c < 4; c++) acc[i][c] = mul2(acc[i][c], a2);
        }

        // ---- stage P^T to smem (float4 per kv-row) ----
        #pragma unroll
        for (int jj = 0; jj < 4; jj++) {
            *(float4*)(Pt + (tx * 4 + jj) * PSTRIDE + ty * 4) =
                make_float4(p[0][jj], p[1][jj], p[2][jj], p[3][jj]);
        }
        __syncthreads();

        // ---- O += P V  (f32x2-packed along output cols) ----
        #pragma unroll 2
        for (int kk = 0; kk < BN; kk++) {
            float4 pv = *(const float4*)(Pt + kk * PSTRIDE + ty * 4);
            const int sw = (kk >> 2) & 7;
            float4 v0 = *(const float4*)(Vs + kk * DH + ((tx * 2)     ^ sw) * 4);
            float4 v1 = *(const float4*)(Vs + kk * DH + ((tx * 2 + 1) ^ sw) * 4);
            u64 vv[4] = { pack2(v0.x, v0.y), pack2(v0.z, v0.w),
                          pack2(v1.x, v1.y), pack2(v1.z, v1.w) };
            u64 pp[4] = { pack2(pv.x, pv.x), pack2(pv.y, pv.y),
                          pack2(pv.z, pv.z), pack2(pv.w, pv.w) };
            #pragma unroll
            for (int i = 0; i < 4; i++)
                #pragma unroll
                for (int c = 0; c < 4; c++)
                    acc[i][c] = fma2(pp[i], vv[c], acc[i][c]);
        }
    }

    // ---- epilogue: O /= l, store ----
    #pragma unroll
    for (int i = 0; i < 4; i++) {
        float inv = 1.0f / l_i[i];
        int srow = q0 + ty * 4 + i;
        float* og = O + (size_t)(b * S + srow) * rowstride + h * DH + tx * 8;
        float2 t0 = unpack2(acc[i][0]);
        float2 t1 = unpack2(acc[i][1]);
        float2 t2 = unpack2(acc[i][2]);
        float2 t3 = unpack2(acc[i][3]);
        *(float4*)(og)     = make_float4(t0.x * inv, t0.y * inv, t1.x * inv, t1.y * inv);
        *(float4*)(og + 4) = make_float4(t2.x * inv, t2.y * inv, t3.x * inv, t3.y * inv);
    }
}

extern "C" void kernel_launch(void* const* d_in, const int* in_sizes, int n_in,
                              void* d_out, int out_size) {
    const float* q = (const float*)d_in[0];
    const float* k = (const float*)d_in[1];
    const float* v = (const float*)d_in[2];
    const int* causal = (const int*)d_in[3];
    float* out = (float*)d_out;

    const int B = 2, H = 16, D = 128;
    const int S = in_sizes[0] / (B * H * D);   // 2048 for this problem

    size_t smem = (size_t)(3 * BM * DH + BN * PSTRIDE) * sizeof(float);  // 115712 B
    cudaFuncSetAttribute(fa_fwd, cudaFuncAttributeMaxDynamicSharedMemorySize, (int)smem);

    dim3 grid(S / BM, H, B);
    fa_fwd<<<grid, NTHREADS, smem>>>(q, k, v, causal, out, S, H);
}